// round 14
// baseline (speedup 1.0000x reference)
#include <cuda_runtime.h>
#include <cuda_fp16.h>
#include <cstdint>

// ============================================================================
// Problem constants
// ============================================================================
namespace {
constexpr int CI = 64, CO = 64, CJ = 16, B_ = 512;
constexpr int HC   = 16;          // i-chunks of 4
constexpr int KT   = 2;           // k-tiles of 16 (K = 32; bias preloaded into C)
constexpr int USTRIDE = 68;       // floats per b-row in Us (64 + 4 pad)
constexpr int SMEM_HALF = 128 * USTRIDE;            // 8704 floats (one U plane)
constexpr int A_HC_U4 = 2 * KT * 4 * 32;            // 512 uint4 per hc (both terms)
constexpr int A_HC_FL = A_HC_U4 * 4;                // 2048 floats
constexpr int SMEM_FLOATS = 2 * SMEM_HALF + 2 * A_HC_FL;     // 21504
constexpr int SMEM_DYN  = SMEM_FLOATS * 4;                   // 86016 bytes
using ull = unsigned long long;
}

// A fragments (fp16): [term][j][hc][kt(2)][mt(4)][lane(32)] x uint4  -> 8.4MB
__device__ uint32_t g_wa[2 * 64 * HC * KT * 4 * 32 * 4];
// B fragments (fp16): [bt(4)][nt(16)][kt(2)][lane(32)] x uint2
__device__ uint32_t g_vb[4 * 16 * KT * 32 * 2];

// ============================================================================
// helpers
// ============================================================================
__device__ __forceinline__ uint32_t pack_h2(float lo, float hi) {
    __half2 h = __floats2half2_rn(lo, hi);
    return *(uint32_t*)&h;
}
__device__ __forceinline__ ull fma2(ull a, ull b, ull c) {
    ull d;
    asm("fma.rn.f32x2 %0, %1, %2, %3;" : "=l"(d) : "l"(a), "l"(b), "l"(c));
    return d;
}
__device__ __forceinline__ ull splat2(float x) {
    ull r;
    asm("mov.b64 %0, {%1, %1};" : "=l"(r) : "f"(x));
    return r;
}
__device__ __forceinline__ ull pack2(float lo, float hi) {
    ull r;
    asm("mov.b64 %0, {%1, %2};" : "=l"(r) : "f"(lo), "f"(hi));
    return r;
}
__device__ __forceinline__ void unpack2(ull v, float& lo, float& hi) {
    asm("mov.b64 {%0, %1}, %2;" : "=f"(lo), "=f"(hi) : "l"(v));
}
__device__ __forceinline__ void mma_f16(float c[4], uint32_t a0, uint32_t a1,
                                        uint32_t a2, uint32_t a3,
                                        uint32_t b0, uint32_t b1) {
    asm volatile(
        "mma.sync.aligned.m16n8k16.row.col.f32.f16.f16.f32 "
        "{%0,%1,%2,%3}, {%4,%5,%6,%7}, {%8,%9}, {%0,%1,%2,%3};"
        : "+f"(c[0]), "+f"(c[1]), "+f"(c[2]), "+f"(c[3])
        : "r"(a0), "r"(a1), "r"(a2), "r"(a3), "r"(b0), "r"(b1));
}
__device__ __forceinline__ void cpa16(uint32_t s, const void* g) {
    asm volatile("cp.async.cg.shared.global [%0], [%1], 16;" :: "r"(s), "l"(g));
}
__device__ __forceinline__ void cp_commit() { asm volatile("cp.async.commit_group;"); }
template <int N>
__device__ __forceinline__ void cp_wait() { asm volatile("cp.async.wait_group %0;" :: "n"(N)); }

// ============================================================================
// Fused prep (validated R10/R11/R13, ~1.6us)
// ============================================================================
__global__ void __launch_bounds__(256) prep_all(
    const float* __restrict__ theta,
    const float* __restrict__ Wc,  const float* __restrict__ Ws,
    const float* __restrict__ Wbc, const float* __restrict__ Wbs)
{
    const int blk = blockIdx.x;
    const int t   = threadIdx.x;

    if (blk < 2048) {
        const int term = blk >> 10;
        const int j    = (blk >> 4) & 63;
        const int hc   = blk & 15;
        const int lane = t & 31, mt = (t >> 5) & 3, kt = t >> 7;
        const int g = lane >> 2, tt = lane & 3;
        const float* T = (kt == 0) ? (term ? Wbc : Wc) : (term ? Wbs : Ws);
        const float* base = T + (size_t)((j * 64 + hc * 4 + mt) * 16 + 2 * tt) * 16;
        uint4 o;
        o.x = pack_h2(base[0 * 16 + g],     base[1 * 16 + g]);
        o.y = pack_h2(base[0 * 16 + g + 8], base[1 * 16 + g + 8]);
        o.z = pack_h2(base[8 * 16 + g],     base[9 * 16 + g]);
        o.w = pack_h2(base[8 * 16 + g + 8], base[9 * 16 + g + 8]);
        ((uint4*)g_wa)[((blk * KT + kt) * 4 + mt) * 32 + lane] = o;
    } else {
        const int v = (blk - 2048) * 256 + t;
        const int lane = v & 31;
        const int kt   = (v >> 5) & 1;
        const int nt   = (v >> 6) & 15;
        const int bt   = v >> 10;
        const int g    = lane >> 2, tt = lane & 3;
        const int b    = bt * 128 + nt * 8 + g;
        const int k0   = kt * 16 + 2 * tt;
        auto vval = [&](int k) -> float {
            return (k < 16) ? cosf(theta[b * CJ + k]) : sinf(theta[b * CJ + (k - 16)]);
        };
        uint2 o;
        o.x = pack_h2(vval(k0),     vval(k0 + 1));
        o.y = pack_h2(vval(k0 + 8), vval(k0 + 9));
        ((uint2*)g_vb)[((bt * 16 + nt) * KT + kt) * 32 + lane] = o;
    }
}

// ============================================================================
// Main kernel — fused-hc steps (3 barriers per hc), F direct from gmem,
// bias preloaded into mma accumulators. grid (4,64), 256 thr, occ 2.
// ============================================================================
__global__ void __launch_bounds__(256, 2) main_kernel(
    const float* __restrict__ F,     // (B, CI, 4, 4)
    const float* __restrict__ Wb,    // bias term1 (flat rr = q*4+r)
    const float* __restrict__ Wbb,   // bias term2 (flat rr = p*4+q)
    float* __restrict__ out)         // (B, CO, 4, 4)
{
    extern __shared__ float sm[];
    float* plane0 = sm;                       // U  (term0) for current hc
    float* plane1 = sm + SMEM_HALF;           // Ub (term1)
    float* A0 = sm + 2 * SMEM_HALF;           // A both-terms double buffer
    float* A1 = A0 + A_HC_FL;

    const int tid  = threadIdx.x;
    const int wid  = tid >> 5;
    const int lane = tid & 31;
    const int bt   = blockIdx.x;
    const int j    = blockIdx.y;
    const int wm   = wid & 1;
    const int wn   = wid >> 1;
    const int gid  = lane >> 2;
    const int tig  = lane & 3;
    const int b_l  = tid >> 1;       // paired lanes share b
    const int p0   = (tid & 1) * 2;

    ull o01[2] = {0ull, 0ull}, o23[2] = {0ull, 0ull};

    // Vb fragments in registers
    uint2 vb[KT][4];
    {
        const uint2* Vb = (const uint2*)g_vb;
#pragma unroll
        for (int kt = 0; kt < KT; kt++)
#pragma unroll
            for (int fn = 0; fn < 4; fn++)
                vb[kt][fn] = Vb[((bt * 16 + wn * 4 + fn) * KT + kt) * 32 + lane];
    }

    // thread's F base (float4 units): F4[(b*64 + i)*4 + row]
    const float4* Fg = ((const float4*)F) + (size_t)(bt * 128 + b_l) * 256;

    // fused both-terms A prefetch for hc
    auto prefetch_A = [&](int hc, float* dst) {
        const uint4* s0 = ((const uint4*)g_wa) + (size_t)((j * 16 + hc) * KT) * 128;
        const uint4* s1 = s0 + (size_t)1024 * KT * 128;   // term stride
        const uint32_t sa = (uint32_t)__cvta_generic_to_shared(dst);
        cpa16(sa + (uint32_t)tid * 16u, s0 + tid);
        cpa16(sa + (uint32_t)(256 + tid) * 16u, s1 + tid);
    };

    // mma for one term: A sub-block + bias preloaded into c
    auto do_mma = [&](float c[2][4][4], const uint4* Asub, const float* bias, int hc) {
#pragma unroll
        for (int fm = 0; fm < 2; fm++) {
            const int i_g = hc * 4 + wm * 2 + fm;
            const float blo = bias[(size_t)(j * 64 + i_g) * 16 + gid];
            const float bhi = bias[(size_t)(j * 64 + i_g) * 16 + gid + 8];
#pragma unroll
            for (int fn = 0; fn < 4; fn++) {
                c[fm][fn][0] = blo; c[fm][fn][1] = blo;
                c[fm][fn][2] = bhi; c[fm][fn][3] = bhi;
            }
        }
#pragma unroll
        for (int kt = 0; kt < KT; kt++) {
            uint4 a[2];
            a[0] = Asub[(kt * 4 + wm * 2 + 0) * 32 + lane];
            a[1] = Asub[(kt * 4 + wm * 2 + 1) * 32 + lane];
#pragma unroll
            for (int fm = 0; fm < 2; fm++)
#pragma unroll
                for (int fn = 0; fn < 4; fn++)
                    mma_f16(c[fm][fn], a[fm].x, a[fm].y, a[fm].z, a[fm].w,
                            vb[kt][fn].x, vb[kt][fn].y);
        }
    };

    auto sts_c = [&](float c[2][4][4], float* plane) {
#pragma unroll
        for (int fm = 0; fm < 2; fm++)
#pragma unroll
            for (int fn = 0; fn < 4; fn++) {
                const int m = (wm * 2 + fm) * 16 + gid;
                const int n = (wn * 4 + fn) * 8 + 2 * tig;
                plane[n * USTRIDE + m]           = c[fm][fn][0];
                plane[(n + 1) * USTRIDE + m]     = c[fm][fn][1];
                plane[n * USTRIDE + m + 8]       = c[fm][fn][2];
                plane[(n + 1) * USTRIDE + m + 8] = c[fm][fn][3];
            }
    };

    // apply term pterm for chunk phc: U from smem plane, F direct from gmem (L1)
    auto apply_prev = [&](int pterm, int phc) {
        const float4* fg = Fg + phc * 16;   // + il*4 + row
        if (pterm == 0) {
            const float* ub = plane0 + b_l * USTRIDE;
#pragma unroll
            for (int il = 0; il < 4; il++) {
                ulonglong2 uq[4];
#pragma unroll
                for (int q = 0; q < 4; q++)
                    uq[q] = *(const ulonglong2*)(ub + il * 16 + q * 4);
#pragma unroll
                for (int pp = 0; pp < 2; pp++) {
                    const float4 f = fg[il * 4 + (p0 + pp)];
                    const float fv[4] = {f.x, f.y, f.z, f.w};
#pragma unroll
                    for (int q = 0; q < 4; q++) {
                        const ull fs = splat2(fv[q]);
                        o01[pp] = fma2(fs, uq[q].x, o01[pp]);
                        o23[pp] = fma2(fs, uq[q].y, o23[pp]);
                    }
                }
            }
        } else {
            const float* ub = plane1 + b_l * USTRIDE;
#pragma unroll
            for (int il = 0; il < 4; il++) {
                ull f01[4], f23[4];
#pragma unroll
                for (int q = 0; q < 4; q++) {
                    const float4 fq = fg[il * 4 + q];
                    f01[q] = pack2(fq.x, fq.y);
                    f23[q] = pack2(fq.z, fq.w);
                }
#pragma unroll
                for (int pp = 0; pp < 2; pp++) {
                    const float4 u = *(const float4*)(ub + il * 16 + (p0 + pp) * 4);
                    const float uv[4] = {u.x, u.y, u.z, u.w};
#pragma unroll
                    for (int q = 0; q < 4; q++) {
                        const ull gs = splat2(uv[q]);
                        o01[pp] = fma2(gs, f01[q], o01[pp]);
                        o23[pp] = fma2(gs, f23[q], o23[pp]);
                    }
                }
            }
        }
    };

    prefetch_A(0, A0);
    cp_commit();

    for (int hc = 0; hc < HC; hc++) {
        cp_wait<0>();
        __syncthreads();                       // BAR1: A(hc) + planes(hc-1) visible

        if (hc + 1 < HC) { prefetch_A(hc + 1, (hc & 1) ? A0 : A1); cp_commit(); }
        const uint4* As = (const uint4*)((hc & 1) ? A1 : A0);

        float c[2][4][4];

        // ---- term0: build U(hc) while applying Ub... no: apply(hc-1, t0) ----
        do_mma(c, As, Wb, hc);
        if (hc > 0) apply_prev(0, hc - 1);     // reads plane0 (old)

        __syncthreads();                       // BAR2
        sts_c(c, plane0);

        // ---- term1 ----
        do_mma(c, As + 256, Wbb, hc);
        if (hc > 0) apply_prev(1, hc - 1);     // reads plane1 (old)

        __syncthreads();                       // BAR3
        sts_c(c, plane1);
    }

    // tail: apply final chunk (both terms)
    __syncthreads();
    apply_prev(0, HC - 1);
    apply_prev(1, HC - 1);

#pragma unroll
    for (int pp = 0; pp < 2; pp++) {
        float4 o;
        unpack2(o01[pp], o.x, o.y);
        unpack2(o23[pp], o.z, o.w);
        ((float4*)out)[(size_t)((bt * 128 + b_l) * 64 + j) * 4 + (p0 + pp)] = o;
    }
}

// ============================================================================
// Launch
// ============================================================================
extern "C" void kernel_launch(void* const* d_in, const int* in_sizes, int n_in,
                              void* d_out, int out_size) {
    (void)in_sizes; (void)n_in; (void)out_size;
    const float* F   = (const float*)d_in[0];
    const float* th  = (const float*)d_in[1];
    const float* Wb  = (const float*)d_in[2];
    const float* Wc  = (const float*)d_in[3];
    const float* Ws  = (const float*)d_in[4];
    const float* Wbb = (const float*)d_in[5];
    const float* Wbc = (const float*)d_in[6];
    const float* Wbs = (const float*)d_in[7];

    cudaFuncSetAttribute(main_kernel, cudaFuncAttributeMaxDynamicSharedMemorySize, SMEM_DYN);

    prep_all<<<2064, 256>>>(th, Wc, Ws, Wbc, Wbs);
    main_kernel<<<dim3(4, 64), 256, SMEM_DYN>>>(F, Wb, Wbb, (float*)d_out);
}

// round 15
// speedup vs baseline: 1.3902x; 1.3902x over previous
#include <cuda_runtime.h>
#include <cuda_fp16.h>
#include <cstdint>

// ============================================================================
// Problem constants
// ============================================================================
namespace {
constexpr int CI = 64, CO = 64, CJ = 16, B_ = 512;
constexpr int HC   = 16;          // i-chunks of 4
constexpr int KT   = 2;           // k-tiles of 16 (K = 32; bias preloaded into C)
constexpr int USTRIDE = 68;       // floats per b-row in Us/Fs (64 + 4 pad)
constexpr int SMEM_HALF = 128 * USTRIDE;            // 8704 floats
constexpr int A_STEP_U4 = KT * 4 * 32;              // 256 uint4 per step
constexpr int A_STEP_FL = A_STEP_U4 * 4;            // 1024 floats
constexpr int SMEM_FLOATS = 2 * SMEM_HALF + 2 * A_STEP_FL;   // 19456
constexpr int SMEM_DYN  = SMEM_FLOATS * 4;                   // 77824 bytes
using ull = unsigned long long;
}

// A fragments (fp16): [term][j][hc][kt(2)][mt(4)][lane(32)] x uint4  -> 8.4MB
__device__ uint32_t g_wa[2 * 64 * HC * KT * 4 * 32 * 4];
// B fragments (fp16): [bt(4)][nt(16)][kt(2)][lane(32)] x uint2
__device__ uint32_t g_vb[4 * 16 * KT * 32 * 2];

// ============================================================================
// helpers
// ============================================================================
__device__ __forceinline__ uint32_t pack_h2(float lo, float hi) {
    __half2 h = __floats2half2_rn(lo, hi);
    return *(uint32_t*)&h;
}
__device__ __forceinline__ ull fma2(ull a, ull b, ull c) {
    ull d;
    asm("fma.rn.f32x2 %0, %1, %2, %3;" : "=l"(d) : "l"(a), "l"(b), "l"(c));
    return d;
}
__device__ __forceinline__ ull splat2(float x) {
    ull r;
    asm("mov.b64 %0, {%1, %1};" : "=l"(r) : "f"(x));
    return r;
}
__device__ __forceinline__ ull pack2(float lo, float hi) {
    ull r;
    asm("mov.b64 %0, {%1, %2};" : "=l"(r) : "f"(lo), "f"(hi));
    return r;
}
__device__ __forceinline__ void unpack2(ull v, float& lo, float& hi) {
    asm("mov.b64 {%0, %1}, %2;" : "=f"(lo), "=f"(hi) : "l"(v));
}
__device__ __forceinline__ void mma_f16(float c[4], uint32_t a0, uint32_t a1,
                                        uint32_t a2, uint32_t a3,
                                        uint32_t b0, uint32_t b1) {
    asm volatile(
        "mma.sync.aligned.m16n8k16.row.col.f32.f16.f16.f32 "
        "{%0,%1,%2,%3}, {%4,%5,%6,%7}, {%8,%9}, {%0,%1,%2,%3};"
        : "+f"(c[0]), "+f"(c[1]), "+f"(c[2]), "+f"(c[3])
        : "r"(a0), "r"(a1), "r"(a2), "r"(a3), "r"(b0), "r"(b1));
}
__device__ __forceinline__ void cpa16(uint32_t s, const void* g) {
    asm volatile("cp.async.cg.shared.global [%0], [%1], 16;" :: "r"(s), "l"(g));
}
__device__ __forceinline__ void cp_commit() { asm volatile("cp.async.commit_group;"); }
template <int N>
__device__ __forceinline__ void cp_wait() { asm volatile("cp.async.wait_group %0;" :: "n"(N)); }

// ============================================================================
// Fused prep (validated R10/R11/R13, ~1.6us): blocks [0,2048) = A-fragments
// via direct sector-coalesced LDG; [2048,2064) = trig B-fragments.
// ============================================================================
__global__ void __launch_bounds__(256) prep_all(
    const float* __restrict__ theta,
    const float* __restrict__ Wc,  const float* __restrict__ Ws,
    const float* __restrict__ Wbc, const float* __restrict__ Wbs)
{
    const int blk = blockIdx.x;
    const int t   = threadIdx.x;

    if (blk < 2048) {
        const int term = blk >> 10;
        const int j    = (blk >> 4) & 63;
        const int hc   = blk & 15;
        const int lane = t & 31, mt = (t >> 5) & 3, kt = t >> 7;
        const int g = lane >> 2, tt = lane & 3;
        const float* T = (kt == 0) ? (term ? Wbc : Wc) : (term ? Wbs : Ws);
        const float* base = T + (size_t)((j * 64 + hc * 4 + mt) * 16 + 2 * tt) * 16;
        uint4 o;
        o.x = pack_h2(base[0 * 16 + g],     base[1 * 16 + g]);
        o.y = pack_h2(base[0 * 16 + g + 8], base[1 * 16 + g + 8]);
        o.z = pack_h2(base[8 * 16 + g],     base[9 * 16 + g]);
        o.w = pack_h2(base[8 * 16 + g + 8], base[9 * 16 + g + 8]);
        ((uint4*)g_wa)[((blk * KT + kt) * 4 + mt) * 32 + lane] = o;
    } else {
        const int v = (blk - 2048) * 256 + t;
        const int lane = v & 31;
        const int kt   = (v >> 5) & 1;
        const int nt   = (v >> 6) & 15;
        const int bt   = v >> 10;
        const int g    = lane >> 2, tt = lane & 3;
        const int b    = bt * 128 + nt * 8 + g;
        const int k0   = kt * 16 + 2 * tt;
        auto vval = [&](int k) -> float {
            return (k < 16) ? cosf(theta[b * CJ + k]) : sinf(theta[b * CJ + (k - 16)]);
        };
        uint2 o;
        o.x = pack_h2(vval(k0),     vval(k0 + 1));
        o.y = pack_h2(vval(k0 + 8), vval(k0 + 9));
        ((uint2*)g_vb)[((bt * 16 + nt) * KT + kt) * 32 + lane] = o;
    }
}

// ============================================================================
// Main kernel — R13 structure (66.1us best) with ONE change: bias preloaded
// into mma accumulators (removes post-mma FADDs; bias LDG latency hides
// under the HMMA block). grid (4,64), 256 thr, occ 2, fp16 mma.
// ============================================================================
__global__ void __launch_bounds__(256, 2) main_kernel(
    const float* __restrict__ F,     // (B, CI, 4, 4)
    const float* __restrict__ Wb,    // bias term1 (flat rr = q*4+r)
    const float* __restrict__ Wbb,   // bias term2 (flat rr = p*4+q)
    float* __restrict__ out)         // (B, CO, 4, 4)
{
    extern __shared__ float sm[];
    float* Us = sm;
    float* Fs = sm + SMEM_HALF;
    float* A0 = sm + 2 * SMEM_HALF;
    float* A1 = A0 + A_STEP_FL;

    const int tid  = threadIdx.x;
    const int wid  = tid >> 5;
    const int lane = tid & 31;
    const int bt   = blockIdx.x;
    const int j    = blockIdx.y;
    const int wm   = wid & 1;
    const int wn   = wid >> 1;
    const int gid  = lane >> 2;
    const int tig  = lane & 3;
    const int b_l  = tid >> 1;       // paired lanes share b (LDS broadcast)
    const int p0   = (tid & 1) * 2;

    ull o01[2] = {0ull, 0ull}, o23[2] = {0ull, 0ull};

    uint2 vb[KT][4];
    {
        const uint2* Vb = (const uint2*)g_vb;
#pragma unroll
        for (int kt = 0; kt < KT; kt++)
#pragma unroll
            for (int fn = 0; fn < 4; fn++)
                vb[kt][fn] = Vb[((bt * 16 + wn * 4 + fn) * KT + kt) * 32 + lane];
    }

    auto prefetch_A = [&](int s, float* dst) {
        const int term = s & 1, hc = s >> 1;
        const uint4* src = ((const uint4*)g_wa) +
                           (size_t)((term * 1024 + j * 16 + hc) * KT) * 128;
        const uint32_t sa = (uint32_t)__cvta_generic_to_shared(dst);
        cpa16(sa + (uint32_t)tid * 16u, src + tid);
    };

    auto stage_F = [&](int hc) {
        const uint32_t sa = (uint32_t)__cvta_generic_to_shared(Fs);
#pragma unroll
        for (int pass = 0; pass < 8; pass++) {
            const int v  = pass * 256 + tid;
            const int bb = v >> 4;
            const int x  = v & 15;
            cpa16(sa + (uint32_t)(bb * USTRIDE + x * 4) * 4u,
                  ((const float4*)F) + (size_t)(bt * 128 + bb) * 256 +
                  (hc * 4 + (x >> 2)) * 4 + (x & 3));
        }
        cp_commit();
    };

    auto apply_prev = [&](int pterm) {
        const float* ub = Us + b_l * USTRIDE;
        const float* fb = Fs + b_l * USTRIDE;
        if (pterm == 0) {
#pragma unroll
            for (int il = 0; il < 4; il++) {
                ulonglong2 uq[4];
#pragma unroll
                for (int q = 0; q < 4; q++)
                    uq[q] = *(const ulonglong2*)(ub + il * 16 + q * 4);
#pragma unroll
                for (int pp = 0; pp < 2; pp++) {
                    const float4 f = *(const float4*)(fb + il * 16 + (p0 + pp) * 4);
                    const float fv[4] = {f.x, f.y, f.z, f.w};
#pragma unroll
                    for (int q = 0; q < 4; q++) {
                        const ull fs = splat2(fv[q]);
                        o01[pp] = fma2(fs, uq[q].x, o01[pp]);
                        o23[pp] = fma2(fs, uq[q].y, o23[pp]);
                    }
                }
            }
        } else {
#pragma unroll
            for (int il = 0; il < 4; il++) {
                ull f01[4], f23[4];
#pragma unroll
                for (int q = 0; q < 4; q++) {
                    const float4 fq = *(const float4*)(fb + il * 16 + q * 4);
                    f01[q] = pack2(fq.x, fq.y);
                    f23[q] = pack2(fq.z, fq.w);
                }
#pragma unroll
                for (int pp = 0; pp < 2; pp++) {
                    const float4 u = *(const float4*)(ub + il * 16 + (p0 + pp) * 4);
                    const float uv[4] = {u.x, u.y, u.z, u.w};
#pragma unroll
                    for (int q = 0; q < 4; q++) {
                        const ull gs = splat2(uv[q]);
                        o01[pp] = fma2(gs, f01[q], o01[pp]);
                        o23[pp] = fma2(gs, f23[q], o23[pp]);
                    }
                }
            }
        }
    };

    prefetch_A(0, A0);
    cp_commit();

    for (int s = 0; s < 2 * HC; s++) {
        const int term = s & 1;
        const int hc   = s >> 1;

        if (s + 1 < 2 * HC) {
            prefetch_A(s + 1, (s & 1) ? A0 : A1);
            cp_commit();
            cp_wait<1>();
        } else {
            cp_wait<0>();
        }
        __syncthreads();

        // ==== interleave: mma(s) + apply(s-1) on disjoint pipes ====
        // bias preloaded into accumulators (mma accumulates on top)
        float c[2][4][4];
        {
            const float* bias = term ? Wbb : Wb;
#pragma unroll
            for (int fm = 0; fm < 2; fm++) {
                const int i_g = hc * 4 + wm * 2 + fm;
                const float blo = bias[(size_t)(j * 64 + i_g) * 16 + gid];
                const float bhi = bias[(size_t)(j * 64 + i_g) * 16 + gid + 8];
#pragma unroll
                for (int fn = 0; fn < 4; fn++) {
                    c[fm][fn][0] = blo; c[fm][fn][1] = blo;
                    c[fm][fn][2] = bhi; c[fm][fn][3] = bhi;
                }
            }
        }

        const uint4* As = (const uint4*)((s & 1) ? A1 : A0);
#pragma unroll
        for (int kt = 0; kt < KT; kt++) {
            uint4 a[2];
            a[0] = As[(kt * 4 + wm * 2 + 0) * 32 + lane];
            a[1] = As[(kt * 4 + wm * 2 + 1) * 32 + lane];
#pragma unroll
            for (int fm = 0; fm < 2; fm++)
#pragma unroll
                for (int fn = 0; fn < 4; fn++)
                    mma_f16(c[fm][fn], a[fm].x, a[fm].y, a[fm].z, a[fm].w,
                            vb[kt][fn].x, vb[kt][fn].y);
        }

        if (s > 0) apply_prev(1 - term);

        __syncthreads();

        // ==== post: store Us(s); stage Fs(hc) on term0 steps ====
#pragma unroll
        for (int fm = 0; fm < 2; fm++)
#pragma unroll
            for (int fn = 0; fn < 4; fn++) {
                const int m = (wm * 2 + fm) * 16 + gid;
                const int n = (wn * 4 + fn) * 8 + 2 * tig;
                Us[n * USTRIDE + m]           = c[fm][fn][0];
                Us[(n + 1) * USTRIDE + m]     = c[fm][fn][1];
                Us[n * USTRIDE + m + 8]       = c[fm][fn][2];
                Us[(n + 1) * USTRIDE + m + 8] = c[fm][fn][3];
            }

        if (term == 0) stage_F(hc);
    }

    // ==== tail ====
    cp_wait<0>();
    __syncthreads();
    apply_prev(1);

#pragma unroll
    for (int pp = 0; pp < 2; pp++) {
        float4 o;
        unpack2(o01[pp], o.x, o.y);
        unpack2(o23[pp], o.z, o.w);
        ((float4*)out)[(size_t)((bt * 128 + b_l) * 64 + j) * 4 + (p0 + pp)] = o;
    }
}

// ============================================================================
// Launch
// ============================================================================
extern "C" void kernel_launch(void* const* d_in, const int* in_sizes, int n_in,
                              void* d_out, int out_size) {
    (void)in_sizes; (void)n_in; (void)out_size;
    const float* F   = (const float*)d_in[0];
    const float* th  = (const float*)d_in[1];
    const float* Wb  = (const float*)d_in[2];
    const float* Wc  = (const float*)d_in[3];
    const float* Ws  = (const float*)d_in[4];
    const float* Wbb = (const float*)d_in[5];
    const float* Wbc = (const float*)d_in[6];
    const float* Wbs = (const float*)d_in[7];

    cudaFuncSetAttribute(main_kernel, cudaFuncAttributeMaxDynamicSharedMemorySize, SMEM_DYN);

    prep_all<<<2064, 256>>>(th, Wc, Ws, Wbc, Wbs);
    main_kernel<<<dim3(4, 64), 256, SMEM_DYN>>>(F, Wb, Wbb, (float*)d_out);
}

// round 16
// speedup vs baseline: 1.4313x; 1.0295x over previous
#include <cuda_runtime.h>
#include <cuda_fp16.h>
#include <cstdint>

// ============================================================================
// Problem constants
// ============================================================================
namespace {
constexpr int CI = 64, CO = 64, CJ = 16, B_ = 512;
constexpr int HC   = 16;          // i-chunks of 4
constexpr int KT   = 2;           // k-tiles of 16 (K = 32; bias post-added from smem)
constexpr int USTRIDE = 68;       // floats per b-row in Us/Fs (64 + 4 pad)
constexpr int SMEM_HALF = 128 * USTRIDE;            // 8704 floats
constexpr int A_STEP_U4 = KT * 4 * 32;              // 256 uint4 per step
constexpr int A_STEP_FL = A_STEP_U4 * 4;            // 1024 floats
constexpr int BIAS_FL   = 2 * 1024;                 // Wb/Wbb j-slices
constexpr int SMEM_FLOATS = 2 * SMEM_HALF + 2 * A_STEP_FL + BIAS_FL;  // 21504
constexpr int SMEM_DYN  = SMEM_FLOATS * 4;                            // 86016 B
using ull = unsigned long long;
}

// A fragments (fp16): [term][j][hc][kt(2)][mt(4)][lane(32)] x uint4  -> 8.4MB
__device__ uint32_t g_wa[2 * 64 * HC * KT * 4 * 32 * 4];
// B fragments (fp16): [bt(4)][nt(16)][kt(2)][lane(32)] x uint2
__device__ uint32_t g_vb[4 * 16 * KT * 32 * 2];

// ============================================================================
// helpers
// ============================================================================
__device__ __forceinline__ uint32_t pack_h2(float lo, float hi) {
    __half2 h = __floats2half2_rn(lo, hi);
    return *(uint32_t*)&h;
}
__device__ __forceinline__ ull fma2(ull a, ull b, ull c) {
    ull d;
    asm("fma.rn.f32x2 %0, %1, %2, %3;" : "=l"(d) : "l"(a), "l"(b), "l"(c));
    return d;
}
__device__ __forceinline__ ull splat2(float x) {
    ull r;
    asm("mov.b64 %0, {%1, %1};" : "=l"(r) : "f"(x));
    return r;
}
__device__ __forceinline__ ull pack2(float lo, float hi) {
    ull r;
    asm("mov.b64 %0, {%1, %2};" : "=l"(r) : "f"(lo), "f"(hi));
    return r;
}
__device__ __forceinline__ void unpack2(ull v, float& lo, float& hi) {
    asm("mov.b64 {%0, %1}, %2;" : "=f"(lo), "=f"(hi) : "l"(v));
}
__device__ __forceinline__ void mma_f16(float c[4], uint32_t a0, uint32_t a1,
                                        uint32_t a2, uint32_t a3,
                                        uint32_t b0, uint32_t b1) {
    asm volatile(
        "mma.sync.aligned.m16n8k16.row.col.f32.f16.f16.f32 "
        "{%0,%1,%2,%3}, {%4,%5,%6,%7}, {%8,%9}, {%0,%1,%2,%3};"
        : "+f"(c[0]), "+f"(c[1]), "+f"(c[2]), "+f"(c[3])
        : "r"(a0), "r"(a1), "r"(a2), "r"(a3), "r"(b0), "r"(b1));
}
__device__ __forceinline__ void cpa16(uint32_t s, const void* g) {
    asm volatile("cp.async.cg.shared.global [%0], [%1], 16;" :: "r"(s), "l"(g));
}
__device__ __forceinline__ void cp_commit() { asm volatile("cp.async.commit_group;"); }
template <int N>
__device__ __forceinline__ void cp_wait() { asm volatile("cp.async.wait_group %0;" :: "n"(N)); }

// ============================================================================
// Fused prep (validated R10/R11/R13, ~1.6us)
// ============================================================================
__global__ void __launch_bounds__(256) prep_all(
    const float* __restrict__ theta,
    const float* __restrict__ Wc,  const float* __restrict__ Ws,
    const float* __restrict__ Wbc, const float* __restrict__ Wbs)
{
    const int blk = blockIdx.x;
    const int t   = threadIdx.x;

    if (blk < 2048) {
        const int term = blk >> 10;
        const int j    = (blk >> 4) & 63;
        const int hc   = blk & 15;
        const int lane = t & 31, mt = (t >> 5) & 3, kt = t >> 7;
        const int g = lane >> 2, tt = lane & 3;
        const float* T = (kt == 0) ? (term ? Wbc : Wc) : (term ? Wbs : Ws);
        const float* base = T + (size_t)((j * 64 + hc * 4 + mt) * 16 + 2 * tt) * 16;
        uint4 o;
        o.x = pack_h2(base[0 * 16 + g],     base[1 * 16 + g]);
        o.y = pack_h2(base[0 * 16 + g + 8], base[1 * 16 + g + 8]);
        o.z = pack_h2(base[8 * 16 + g],     base[9 * 16 + g]);
        o.w = pack_h2(base[8 * 16 + g + 8], base[9 * 16 + g + 8]);
        ((uint4*)g_wa)[((blk * KT + kt) * 4 + mt) * 32 + lane] = o;
    } else {
        const int v = (blk - 2048) * 256 + t;
        const int lane = v & 31;
        const int kt   = (v >> 5) & 1;
        const int nt   = (v >> 6) & 15;
        const int bt   = v >> 10;
        const int g    = lane >> 2, tt = lane & 3;
        const int b    = bt * 128 + nt * 8 + g;
        const int k0   = kt * 16 + 2 * tt;
        auto vval = [&](int k) -> float {
            return (k < 16) ? cosf(theta[b * CJ + k]) : sinf(theta[b * CJ + (k - 16)]);
        };
        uint2 o;
        o.x = pack_h2(vval(k0),     vval(k0 + 1));
        o.y = pack_h2(vval(k0 + 8), vval(k0 + 9));
        ((uint2*)g_vb)[((bt * 16 + nt) * KT + kt) * 32 + lane] = o;
    }
}

// ============================================================================
// Main kernel — R13 structure exactly (66.1us best), with ONE change:
// per-step bias LDGs replaced by a one-time smem staging of the j-slice
// (8KB), read in-loop via broadcast LDS. grid (4,64), 256 thr, occ 2.
// ============================================================================
__global__ void __launch_bounds__(256, 2) main_kernel(
    const float* __restrict__ F,     // (B, CI, 4, 4)
    const float* __restrict__ Wb,    // bias term1 (flat rr = q*4+r)
    const float* __restrict__ Wbb,   // bias term2 (flat rr = p*4+q)
    float* __restrict__ out)         // (B, CO, 4, 4)
{
    extern __shared__ float sm[];
    float* Us = sm;
    float* Fs = sm + SMEM_HALF;
    float* A0 = sm + 2 * SMEM_HALF;
    float* A1 = A0 + A_STEP_FL;
    float* sB = A1 + A_STEP_FL;      // [term*1024 + i_g*16 + rr]

    const int tid  = threadIdx.x;
    const int wid  = tid >> 5;
    const int lane = tid & 31;
    const int bt   = blockIdx.x;
    const int j    = blockIdx.y;
    const int wm   = wid & 1;
    const int wn   = wid >> 1;
    const int gid  = lane >> 2;
    const int tig  = lane & 3;
    const int b_l  = tid >> 1;       // paired lanes share b (LDS broadcast)
    const int p0   = (tid & 1) * 2;

    ull o01[2] = {0ull, 0ull}, o23[2] = {0ull, 0ull};

    // one-time bias staging: 512 float4 over 256 threads (2 each), coalesced
    {
        const float4* b0 = (const float4*)(Wb  + (size_t)j * 1024);
        const float4* b1 = (const float4*)(Wbb + (size_t)j * 1024);
        float4* d = (float4*)sB;
        d[tid]       = b0[tid];
        d[256 + tid] = b1[tid];
        // visibility guaranteed by the first step's __syncthreads
    }

    uint2 vb[KT][4];
    {
        const uint2* Vb = (const uint2*)g_vb;
#pragma unroll
        for (int kt = 0; kt < KT; kt++)
#pragma unroll
            for (int fn = 0; fn < 4; fn++)
                vb[kt][fn] = Vb[((bt * 16 + wn * 4 + fn) * KT + kt) * 32 + lane];
    }

    auto prefetch_A = [&](int s, float* dst) {
        const int term = s & 1, hc = s >> 1;
        const uint4* src = ((const uint4*)g_wa) +
                           (size_t)((term * 1024 + j * 16 + hc) * KT) * 128;
        const uint32_t sa = (uint32_t)__cvta_generic_to_shared(dst);
        cpa16(sa + (uint32_t)tid * 16u, src + tid);
    };

    auto stage_F = [&](int hc) {
        const uint32_t sa = (uint32_t)__cvta_generic_to_shared(Fs);
#pragma unroll
        for (int pass = 0; pass < 8; pass++) {
            const int v  = pass * 256 + tid;
            const int bb = v >> 4;
            const int x  = v & 15;
            cpa16(sa + (uint32_t)(bb * USTRIDE + x * 4) * 4u,
                  ((const float4*)F) + (size_t)(bt * 128 + bb) * 256 +
                  (hc * 4 + (x >> 2)) * 4 + (x & 3));
        }
        cp_commit();
    };

    auto apply_prev = [&](int pterm) {
        const float* ub = Us + b_l * USTRIDE;
        const float* fb = Fs + b_l * USTRIDE;
        if (pterm == 0) {
#pragma unroll
            for (int il = 0; il < 4; il++) {
                ulonglong2 uq[4];
#pragma unroll
                for (int q = 0; q < 4; q++)
                    uq[q] = *(const ulonglong2*)(ub + il * 16 + q * 4);
#pragma unroll
                for (int pp = 0; pp < 2; pp++) {
                    const float4 f = *(const float4*)(fb + il * 16 + (p0 + pp) * 4);
                    const float fv[4] = {f.x, f.y, f.z, f.w};
#pragma unroll
                    for (int q = 0; q < 4; q++) {
                        const ull fs = splat2(fv[q]);
                        o01[pp] = fma2(fs, uq[q].x, o01[pp]);
                        o23[pp] = fma2(fs, uq[q].y, o23[pp]);
                    }
                }
            }
        } else {
#pragma unroll
            for (int il = 0; il < 4; il++) {
                ull f01[4], f23[4];
#pragma unroll
                for (int q = 0; q < 4; q++) {
                    const float4 fq = *(const float4*)(fb + il * 16 + q * 4);
                    f01[q] = pack2(fq.x, fq.y);
                    f23[q] = pack2(fq.z, fq.w);
                }
#pragma unroll
                for (int pp = 0; pp < 2; pp++) {
                    const float4 u = *(const float4*)(ub + il * 16 + (p0 + pp) * 4);
                    const float uv[4] = {u.x, u.y, u.z, u.w};
#pragma unroll
                    for (int q = 0; q < 4; q++) {
                        const ull gs = splat2(uv[q]);
                        o01[pp] = fma2(gs, f01[q], o01[pp]);
                        o23[pp] = fma2(gs, f23[q], o23[pp]);
                    }
                }
            }
        }
    };

    prefetch_A(0, A0);
    cp_commit();

    for (int s = 0; s < 2 * HC; s++) {
        const int term = s & 1;
        const int hc   = s >> 1;

        if (s + 1 < 2 * HC) {
            prefetch_A(s + 1, (s & 1) ? A0 : A1);
            cp_commit();
            cp_wait<1>();
        } else {
            cp_wait<0>();
        }
        __syncthreads();

        // ==== interleave: mma(s) + apply(s-1) on disjoint pipes ====
        float c[2][4][4];
#pragma unroll
        for (int fm = 0; fm < 2; fm++)
#pragma unroll
            for (int fn = 0; fn < 4; fn++)
#pragma unroll
                for (int e = 0; e < 4; e++) c[fm][fn][e] = 0.0f;

        const uint4* As = (const uint4*)((s & 1) ? A1 : A0);
#pragma unroll
        for (int kt = 0; kt < KT; kt++) {
            uint4 a[2];
            a[0] = As[(kt * 4 + wm * 2 + 0) * 32 + lane];
            a[1] = As[(kt * 4 + wm * 2 + 1) * 32 + lane];
#pragma unroll
            for (int fm = 0; fm < 2; fm++)
#pragma unroll
                for (int fn = 0; fn < 4; fn++)
                    mma_f16(c[fm][fn], a[fm].x, a[fm].y, a[fm].z, a[fm].w,
                            vb[kt][fn].x, vb[kt][fn].y);
        }

        if (s > 0) apply_prev(1 - term);

        // bias add in fp32 — broadcast LDS from the staged j-slice
        {
            const float* bias_s = sB + term * 1024;
#pragma unroll
            for (int fm = 0; fm < 2; fm++) {
                const int i_g = hc * 4 + wm * 2 + fm;
                const float blo = bias_s[i_g * 16 + gid];
                const float bhi = bias_s[i_g * 16 + gid + 8];
#pragma unroll
                for (int fn = 0; fn < 4; fn++) {
                    c[fm][fn][0] += blo;
                    c[fm][fn][1] += blo;
                    c[fm][fn][2] += bhi;
                    c[fm][fn][3] += bhi;
                }
            }
        }

        __syncthreads();

        // ==== post: store Us(s); stage Fs(hc) on term0 steps ====
#pragma unroll
        for (int fm = 0; fm < 2; fm++)
#pragma unroll
            for (int fn = 0; fn < 4; fn++) {
                const int m = (wm * 2 + fm) * 16 + gid;
                const int n = (wn * 4 + fn) * 8 + 2 * tig;
                Us[n * USTRIDE + m]           = c[fm][fn][0];
                Us[(n + 1) * USTRIDE + m]     = c[fm][fn][1];
                Us[n * USTRIDE + m + 8]       = c[fm][fn][2];
                Us[(n + 1) * USTRIDE + m + 8] = c[fm][fn][3];
            }

        if (term == 0) stage_F(hc);
    }

    // ==== tail ====
    cp_wait<0>();
    __syncthreads();
    apply_prev(1);

#pragma unroll
    for (int pp = 0; pp < 2; pp++) {
        float4 o;
        unpack2(o01[pp], o.x, o.y);
        unpack2(o23[pp], o.z, o.w);
        ((float4*)out)[(size_t)((bt * 128 + b_l) * 64 + j) * 4 + (p0 + pp)] = o;
    }
}

// ============================================================================
// Launch
// ============================================================================
extern "C" void kernel_launch(void* const* d_in, const int* in_sizes, int n_in,
                              void* d_out, int out_size) {
    (void)in_sizes; (void)n_in; (void)out_size;
    const float* F   = (const float*)d_in[0];
    const float* th  = (const float*)d_in[1];
    const float* Wb  = (const float*)d_in[2];
    const float* Wc  = (const float*)d_in[3];
    const float* Ws  = (const float*)d_in[4];
    const float* Wbb = (const float*)d_in[5];
    const float* Wbc = (const float*)d_in[6];
    const float* Wbs = (const float*)d_in[7];

    cudaFuncSetAttribute(main_kernel, cudaFuncAttributeMaxDynamicSharedMemorySize, SMEM_DYN);

    prep_all<<<2064, 256>>>(th, Wc, Ws, Wbc, Wbs);
    main_kernel<<<dim3(4, 64), 256, SMEM_DYN>>>(F, Wb, Wbb, (float*)d_out);
}

// round 17
// speedup vs baseline: 1.5881x; 1.1096x over previous
#include <cuda_runtime.h>
#include <cuda_fp16.h>
#include <cstdint>

// ============================================================================
// Problem constants
// ============================================================================
namespace {
constexpr int CI = 64, CO = 64, CJ = 16, B_ = 512;
constexpr int HC   = 16;          // i-chunks of 4
constexpr int KT   = 2;           // k-tiles of 16 (K = 32; bias post-added from smem)
// fp16 tile rows: 128 B used per b, stride 144 B (odd multiple of 16B class)
constexpr int ROW_B   = 144;                       // bytes per b-row (Us16/Fs16)
constexpr int US_BYTES = 128 * ROW_B;              // 18432
constexpr int A_STEP_U4 = KT * 4 * 32;             // 256 uint4 per step
constexpr int A_BYTES   = A_STEP_U4 * 16;          // 4096
// layout: Us16 | Fs16 | A0 | A1 | bias(8KB)
constexpr int OFF_FS = US_BYTES;                   // 18432
constexpr int OFF_A0 = 2 * US_BYTES;               // 36864
constexpr int OFF_A1 = OFF_A0 + A_BYTES;           // 40960
constexpr int OFF_SB = OFF_A1 + A_BYTES;           // 45056
constexpr int SMEM_DYN = OFF_SB + 2 * 1024 * 4;    // 53248
using ull = unsigned long long;
}

// A fragments (fp16): [term][j][hc][kt(2)][mt(4)][lane(32)] x uint4  -> 8.4MB
__device__ uint32_t g_wa[2 * 64 * HC * KT * 4 * 32 * 4];
// B fragments (fp16): [bt(4)][nt(16)][kt(2)][lane(32)] x uint2
__device__ uint32_t g_vb[4 * 16 * KT * 32 * 2];
// F converted to fp16, flat [b][i][p][q] halves, as uint4 chunks (1MB)
__device__ uint4 g_fh4[65536];

// ============================================================================
// helpers
// ============================================================================
__device__ __forceinline__ uint32_t pack_h2(float lo, float hi) {
    __half2 h = __floats2half2_rn(lo, hi);
    return *(uint32_t*)&h;
}
__device__ __forceinline__ float2 h2f2(uint32_t h) {
    return __half22float2(*(__half2*)&h);
}
__device__ __forceinline__ ull fma2(ull a, ull b, ull c) {
    ull d;
    asm("fma.rn.f32x2 %0, %1, %2, %3;" : "=l"(d) : "l"(a), "l"(b), "l"(c));
    return d;
}
__device__ __forceinline__ ull splat2(float x) {
    ull r;
    asm("mov.b64 %0, {%1, %1};" : "=l"(r) : "f"(x));
    return r;
}
__device__ __forceinline__ ull pack2(float lo, float hi) {
    ull r;
    asm("mov.b64 %0, {%1, %2};" : "=l"(r) : "f"(lo), "f"(hi));
    return r;
}
__device__ __forceinline__ void unpack2(ull v, float& lo, float& hi) {
    asm("mov.b64 {%0, %1}, %2;" : "=f"(lo), "=f"(hi) : "l"(v));
}
__device__ __forceinline__ void mma_f16(float c[4], uint32_t a0, uint32_t a1,
                                        uint32_t a2, uint32_t a3,
                                        uint32_t b0, uint32_t b1) {
    asm volatile(
        "mma.sync.aligned.m16n8k16.row.col.f32.f16.f16.f32 "
        "{%0,%1,%2,%3}, {%4,%5,%6,%7}, {%8,%9}, {%0,%1,%2,%3};"
        : "+f"(c[0]), "+f"(c[1]), "+f"(c[2]), "+f"(c[3])
        : "r"(a0), "r"(a1), "r"(a2), "r"(a3), "r"(b0), "r"(b1));
}
__device__ __forceinline__ void cpa16(uint32_t s, const void* g) {
    asm volatile("cp.async.cg.shared.global [%0], [%1], 16;" :: "r"(s), "l"(g));
}
__device__ __forceinline__ void cp_commit() { asm volatile("cp.async.commit_group;"); }
template <int N>
__device__ __forceinline__ void cp_wait() { asm volatile("cp.async.wait_group %0;" :: "n"(N)); }

// ============================================================================
// Fused prep: [0,2048) A-frags; [2048,2064) trig B-frags; [2064,2320) F->fp16
// ============================================================================
__global__ void __launch_bounds__(256) prep_all(
    const float* __restrict__ theta, const float* __restrict__ F,
    const float* __restrict__ Wc,  const float* __restrict__ Ws,
    const float* __restrict__ Wbc, const float* __restrict__ Wbs)
{
    const int blk = blockIdx.x;
    const int t   = threadIdx.x;

    if (blk < 2048) {
        const int term = blk >> 10;
        const int j    = (blk >> 4) & 63;
        const int hc   = blk & 15;
        const int lane = t & 31, mt = (t >> 5) & 3, kt = t >> 7;
        const int g = lane >> 2, tt = lane & 3;
        const float* T = (kt == 0) ? (term ? Wbc : Wc) : (term ? Wbs : Ws);
        const float* base = T + (size_t)((j * 64 + hc * 4 + mt) * 16 + 2 * tt) * 16;
        uint4 o;
        o.x = pack_h2(base[0 * 16 + g],     base[1 * 16 + g]);
        o.y = pack_h2(base[0 * 16 + g + 8], base[1 * 16 + g + 8]);
        o.z = pack_h2(base[8 * 16 + g],     base[9 * 16 + g]);
        o.w = pack_h2(base[8 * 16 + g + 8], base[9 * 16 + g + 8]);
        ((uint4*)g_wa)[((blk * KT + kt) * 4 + mt) * 32 + lane] = o;
    } else if (blk < 2064) {
        const int v = (blk - 2048) * 256 + t;
        const int lane = v & 31;
        const int kt   = (v >> 5) & 1;
        const int nt   = (v >> 6) & 15;
        const int bt   = v >> 10;
        const int g    = lane >> 2, tt = lane & 3;
        const int b    = bt * 128 + nt * 8 + g;
        const int k0   = kt * 16 + 2 * tt;
        auto vval = [&](int k) -> float {
            return (k < 16) ? cosf(theta[b * CJ + k]) : sinf(theta[b * CJ + (k - 16)]);
        };
        uint2 o;
        o.x = pack_h2(vval(k0),     vval(k0 + 1));
        o.y = pack_h2(vval(k0 + 8), vval(k0 + 9));
        ((uint2*)g_vb)[((bt * 16 + nt) * KT + kt) * 32 + lane] = o;
    } else {
        // F -> fp16: each thread converts 8 floats (one uint4 of halves)
        const int idx = (blk - 2064) * 256 + t;      // [0, 65536)
        const float4 f0 = ((const float4*)F)[idx * 2];
        const float4 f1 = ((const float4*)F)[idx * 2 + 1];
        uint4 o;
        o.x = pack_h2(f0.x, f0.y);
        o.y = pack_h2(f0.z, f0.w);
        o.z = pack_h2(f1.x, f1.y);
        o.w = pack_h2(f1.z, f1.w);
        g_fh4[idx] = o;
    }
}

// ============================================================================
// Main kernel — R16 structure, Us/Fs tiles in fp16 (halved apply LDS bytes).
// grid (4,64), 256 thr, occ 2, fp16 mma, fp32 accumulation everywhere.
// ============================================================================
__global__ void __launch_bounds__(256, 2) main_kernel(
    const float* __restrict__ Wb,    // bias term1 (flat rr = q*4+r)
    const float* __restrict__ Wbb,   // bias term2 (flat rr = p*4+q)
    float* __restrict__ out)         // (B, CO, 4, 4)
{
    extern __shared__ __align__(16) char smb[];
    char*  UsB = smb;
    char*  FsB = smb + OFF_FS;
    float* A0  = (float*)(smb + OFF_A0);
    float* A1  = (float*)(smb + OFF_A1);
    float* sB  = (float*)(smb + OFF_SB);

    const int tid  = threadIdx.x;
    const int wid  = tid >> 5;
    const int lane = tid & 31;
    const int bt   = blockIdx.x;
    const int j    = blockIdx.y;
    const int wm   = wid & 1;
    const int wn   = wid >> 1;
    const int gid  = lane >> 2;
    const int tig  = lane & 3;
    const int b_l  = tid >> 1;       // paired lanes share b
    const int p0   = (tid & 1) * 2;

    ull o01[2] = {0ull, 0ull}, o23[2] = {0ull, 0ull};

    // one-time bias staging (visibility via first step's __syncthreads)
    {
        const float4* b0 = (const float4*)(Wb  + (size_t)j * 1024);
        const float4* b1 = (const float4*)(Wbb + (size_t)j * 1024);
        float4* d = (float4*)sB;
        d[tid]       = b0[tid];
        d[256 + tid] = b1[tid];
    }

    uint2 vb[KT][4];
    {
        const uint2* Vb = (const uint2*)g_vb;
#pragma unroll
        for (int kt = 0; kt < KT; kt++)
#pragma unroll
            for (int fn = 0; fn < 4; fn++)
                vb[kt][fn] = Vb[((bt * 16 + wn * 4 + fn) * KT + kt) * 32 + lane];
    }

    auto prefetch_A = [&](int s, float* dst) {
        const int term = s & 1, hc = s >> 1;
        const uint4* src = ((const uint4*)g_wa) +
                           (size_t)((term * 1024 + j * 16 + hc) * KT) * 128;
        const uint32_t sa = (uint32_t)__cvta_generic_to_shared(dst);
        cpa16(sa + (uint32_t)tid * 16u, src + tid);
    };

    // stage F(hc) fp16 tile: 128 b x 128B, 4 cp.async/thread
    auto stage_F = [&](int hc) {
        const uint32_t sa = (uint32_t)__cvta_generic_to_shared(FsB);
        const char* src = (const char*)g_fh4;
#pragma unroll
        for (int pass = 0; pass < 4; pass++) {
            const int v  = pass * 256 + tid;   // 0..1023
            const int bb = v >> 3;
            const int ch = v & 7;
            cpa16(sa + (uint32_t)(bb * ROW_B + ch * 16),
                  src + (size_t)(bt * 128 + bb) * 2048 + hc * 128 + ch * 16);
        }
        cp_commit();
    };

    auto apply_prev = [&](int pterm) {
        const char* ubB = UsB + b_l * ROW_B;
        const char* fbB = FsB + b_l * ROW_B;
        if (pterm == 0) {
            // out[p][r] += sum_q F[p][q] * U[(il,q,r)]
#pragma unroll
            for (int il = 0; il < 4; il++) {
                const uint4 ha = *(const uint4*)(ubB + il * 32);       // q0,q1
                const uint4 hb = *(const uint4*)(ubB + il * 32 + 16);  // q2,q3
                ull uqx[4], uqy[4];
                { float2 v = h2f2(ha.x); uqx[0] = pack2(v.x, v.y); }
                { float2 v = h2f2(ha.y); uqy[0] = pack2(v.x, v.y); }
                { float2 v = h2f2(ha.z); uqx[1] = pack2(v.x, v.y); }
                { float2 v = h2f2(ha.w); uqy[1] = pack2(v.x, v.y); }
                { float2 v = h2f2(hb.x); uqx[2] = pack2(v.x, v.y); }
                { float2 v = h2f2(hb.y); uqy[2] = pack2(v.x, v.y); }
                { float2 v = h2f2(hb.z); uqx[3] = pack2(v.x, v.y); }
                { float2 v = h2f2(hb.w); uqy[3] = pack2(v.x, v.y); }
                // F rows p0, p0+1: 8 halves, one 16B load
                const uint4 hf = *(const uint4*)(fbB + il * 32 + p0 * 8);
                const float2 fa = h2f2(hf.x), fb2 = h2f2(hf.y);   // p0: q0..q3
                const float2 fc = h2f2(hf.z), fd = h2f2(hf.w);    // p0+1
                const float fv0[4] = {fa.x, fa.y, fb2.x, fb2.y};
                const float fv1[4] = {fc.x, fc.y, fd.x, fd.y};
#pragma unroll
                for (int q = 0; q < 4; q++) {
                    ull fs = splat2(fv0[q]);
                    o01[0] = fma2(fs, uqx[q], o01[0]);
                    o23[0] = fma2(fs, uqy[q], o23[0]);
                    fs = splat2(fv1[q]);
                    o01[1] = fma2(fs, uqx[q], o01[1]);
                    o23[1] = fma2(fs, uqy[q], o23[1]);
                }
            }
        } else {
            // out[p][r] += sum_q Ub[(il,p,q)] * F[q][r]
#pragma unroll
            for (int il = 0; il < 4; il++) {
                const uint4 ga = *(const uint4*)(fbB + il * 32);       // q0,q1 (r01,r23)
                const uint4 gb = *(const uint4*)(fbB + il * 32 + 16);  // q2,q3
                ull f01[4], f23[4];
                { float2 v = h2f2(ga.x); f01[0] = pack2(v.x, v.y); }
                { float2 v = h2f2(ga.y); f23[0] = pack2(v.x, v.y); }
                { float2 v = h2f2(ga.z); f01[1] = pack2(v.x, v.y); }
                { float2 v = h2f2(ga.w); f23[1] = pack2(v.x, v.y); }
                { float2 v = h2f2(gb.x); f01[2] = pack2(v.x, v.y); }
                { float2 v = h2f2(gb.y); f23[2] = pack2(v.x, v.y); }
                { float2 v = h2f2(gb.z); f01[3] = pack2(v.x, v.y); }
                { float2 v = h2f2(gb.w); f23[3] = pack2(v.x, v.y); }
                // Ub rows p0, p0+1: 8 halves, one 16B load
                const uint4 hu = *(const uint4*)(ubB + il * 32 + p0 * 8);
                const float2 ua = h2f2(hu.x), ub2 = h2f2(hu.y);   // p0: q0..q3
                const float2 uc = h2f2(hu.z), ud = h2f2(hu.w);    // p0+1
                const float uv0[4] = {ua.x, ua.y, ub2.x, ub2.y};
                const float uv1[4] = {uc.x, uc.y, ud.x, ud.y};
#pragma unroll
                for (int q = 0; q < 4; q++) {
                    ull gs = splat2(uv0[q]);
                    o01[0] = fma2(gs, f01[q], o01[0]);
                    o23[0] = fma2(gs, f23[q], o23[0]);
                    gs = splat2(uv1[q]);
                    o01[1] = fma2(gs, f01[q], o01[1]);
                    o23[1] = fma2(gs, f23[q], o23[1]);
                }
            }
        }
    };

    prefetch_A(0, A0);
    cp_commit();

    for (int s = 0; s < 2 * HC; s++) {
        const int term = s & 1;
        const int hc   = s >> 1;

        if (s + 1 < 2 * HC) {
            prefetch_A(s + 1, (s & 1) ? A0 : A1);
            cp_commit();
            cp_wait<1>();
        } else {
            cp_wait<0>();
        }
        __syncthreads();

        // ==== interleave: mma(s) + apply(s-1) ====
        float c[2][4][4];
#pragma unroll
        for (int fm = 0; fm < 2; fm++)
#pragma unroll
            for (int fn = 0; fn < 4; fn++)
#pragma unroll
                for (int e = 0; e < 4; e++) c[fm][fn][e] = 0.0f;

        const uint4* As = (const uint4*)((s & 1) ? A1 : A0);
#pragma unroll
        for (int kt = 0; kt < KT; kt++) {
            uint4 a[2];
            a[0] = As[(kt * 4 + wm * 2 + 0) * 32 + lane];
            a[1] = As[(kt * 4 + wm * 2 + 1) * 32 + lane];
#pragma unroll
            for (int fm = 0; fm < 2; fm++)
#pragma unroll
                for (int fn = 0; fn < 4; fn++)
                    mma_f16(c[fm][fn], a[fm].x, a[fm].y, a[fm].z, a[fm].w,
                            vb[kt][fn].x, vb[kt][fn].y);
        }

        if (s > 0) apply_prev(1 - term);

        // bias add in fp32 from staged smem (broadcast LDS)
        {
            const float* bias_s = sB + term * 1024;
#pragma unroll
            for (int fm = 0; fm < 2; fm++) {
                const int i_g = hc * 4 + wm * 2 + fm;
                const float blo = bias_s[i_g * 16 + gid];
                const float bhi = bias_s[i_g * 16 + gid + 8];
#pragma unroll
                for (int fn = 0; fn < 4; fn++) {
                    c[fm][fn][0] += blo;
                    c[fm][fn][1] += blo;
                    c[fm][fn][2] += bhi;
                    c[fm][fn][3] += bhi;
                }
            }
        }

        __syncthreads();

        // ==== post: store Us(s) as fp16; stage Fs(hc) on term0 steps ====
        {
            __half* U16 = (__half*)UsB;
#pragma unroll
            for (int fm = 0; fm < 2; fm++)
#pragma unroll
                for (int fn = 0; fn < 4; fn++) {
                    const int m = (wm * 2 + fm) * 16 + gid;
                    const int n = (wn * 4 + fn) * 8 + 2 * tig;
                    __half* r0 = (__half*)(UsB + n * ROW_B);
                    __half* r1 = (__half*)(UsB + (n + 1) * ROW_B);
                    r0[m]     = __float2half_rn(c[fm][fn][0]);
                    r1[m]     = __float2half_rn(c[fm][fn][1]);
                    r0[m + 8] = __float2half_rn(c[fm][fn][2]);
                    r1[m + 8] = __float2half_rn(c[fm][fn][3]);
                }
            (void)U16;
        }

        if (term == 0) stage_F(hc);
    }

    // ==== tail ====
    cp_wait<0>();
    __syncthreads();
    apply_prev(1);

#pragma unroll
    for (int pp = 0; pp < 2; pp++) {
        float4 o;
        unpack2(o01[pp], o.x, o.y);
        unpack2(o23[pp], o.z, o.w);
        ((float4*)out)[(size_t)((bt * 128 + b_l) * 64 + j) * 4 + (p0 + pp)] = o;
    }
}

// ============================================================================
// Launch
// ============================================================================
extern "C" void kernel_launch(void* const* d_in, const int* in_sizes, int n_in,
                              void* d_out, int out_size) {
    (void)in_sizes; (void)n_in; (void)out_size;
    const float* F   = (const float*)d_in[0];
    const float* th  = (const float*)d_in[1];
    const float* Wb  = (const float*)d_in[2];
    const float* Wc  = (const float*)d_in[3];
    const float* Ws  = (const float*)d_in[4];
    const float* Wbb = (const float*)d_in[5];
    const float* Wbc = (const float*)d_in[6];
    const float* Wbs = (const float*)d_in[7];

    cudaFuncSetAttribute(main_kernel, cudaFuncAttributeMaxDynamicSharedMemorySize, SMEM_DYN);

    prep_all<<<2320, 256>>>(th, F, Wc, Ws, Wbc, Wbs);
    main_kernel<<<dim3(4, 64), 256, SMEM_DYN>>>(Wb, Wbb, (float*)d_out);
}